// round 2
// baseline (speedup 1.0000x reference)
#include <cuda_runtime.h>
#include <math.h>

// Problem constants
#define B_TOTAL     2048
#define DIM         64
#define NODES_TOTAL 65535
#define SPLIT       8
#define NSUB        256      // 2^SPLIT subtrees
#define SUB_NODES   255      // internal nodes per subtree (8 levels)
#define BT          64       // batch tile per CTA

// Device scratch (static — no allocations allowed)
__device__ float g_kdiff[NODES_TOTAL * DIM];     // k0 - k1 per node
__device__ float g_probs8[NSUB * B_TOTAL];       // [depth8_leaf][batch]

// Shared memory layout (in floats)
#define QS_STRIDE 68
#define KD_STRIDE 260
#define SG_STRIDE 257
#define QS_OFF   0
#define KD_OFF   (QS_OFF + 64 * QS_STRIDE)             // 4352
#define SIG_OFF  (KD_OFF + 64 * KD_STRIDE)             // 20992
#define CUM_OFF  (SIG_OFF + 64 * SG_STRIDE)            // 37440
#define SMEM_FLOATS (CUM_OFF + 256 * 64)               // 53824
#define V_OFF    0   // V aliases Q+K region (dead after GEMM1); 16384 <= 20992
#define SMEM_BYTES (SMEM_FLOATS * 4)                   // 215,296 B

// ---------------------------------------------------------------------------
// K0: kdiff[n][k] = tree_key[n][0][k] - tree_key[n][1][k]
// ---------------------------------------------------------------------------
__global__ void kdiff_kernel(const float* __restrict__ tk) {
    int total = NODES_TOTAL * DIM;
    for (int i = blockIdx.x * blockDim.x + threadIdx.x; i < total;
         i += gridDim.x * blockDim.x) {
        int n = i >> 6, k = i & 63;
        g_kdiff[i] = tk[(n << 7) + k] - tk[(n << 7) + 64 + k];
    }
}

// ---------------------------------------------------------------------------
// Main kernel.  PHASE2=false: top 8 levels -> g_probs8.
//               PHASE2=true : one subtree x 64-batch tile -> atomicAdd(out).
//
// Leaf positions inside a (sub)tree use LSB-first path encoding ("pos"):
// expansion level e writes child0 in place at pos, child1 at pos + 2^e.
// Standard (reference) leaf index = bitrev8(pos); kdiff rows and V rows are
// loaded pre-permuted so all in-kernel indexing is pos-order.
// ---------------------------------------------------------------------------
template <bool PHASE2>
__global__ __launch_bounds__(256, 1)
void tree_kernel(const float* __restrict__ q,
                 const float* __restrict__ vtree,
                 float* __restrict__ out)
{
    extern __shared__ float sm[];
    const int tid    = threadIdx.x;
    const int s      = PHASE2 ? blockIdx.x : 0;                 // subtree id
    const int b_base = (PHASE2 ? blockIdx.y : blockIdx.x) * BT; // batch tile

    const int w = tid >> 5, l = tid & 31;

    // ---- Load Q transposed: Qs[k][b], warp-per-row, lane = 2 floats ----
    for (int b = w; b < BT; b += 8) {
        float2 v = *(const float2*)(q + (size_t)(b_base + b) * DIM + 2 * l);
        sm[QS_OFF + (2 * l)     * QS_STRIDE + b] = v.x;
        sm[QS_OFF + (2 * l + 1) * QS_STRIDE + b] = v.y;
    }

    // ---- Load kdiff transposed, rows in pos-order heap layout ----
    for (int r = w; r < SUB_NODES; r += 8) {
        int rp = r + 1;
        int e  = 31 - __clz(rp);          // level within (sub)tree, 0..7
        int posj = rp - (1 << e);         // LSB-first within-level position
        int j  = e ? (int)(__brev((unsigned)posj) >> (32 - e)) : 0; // std idx
        int lvl = e + (PHASE2 ? SPLIT : 0);
        long node = ((1L << lvl) - 1) + (long)s * (1 << e) + j;
        const float* src = g_kdiff + node * DIM;
        float2 v = *(const float2*)(src + 2 * l);
        sm[KD_OFF + (2 * l)     * KD_STRIDE + r] = v.x;
        sm[KD_OFF + (2 * l + 1) * KD_STRIDE + r] = v.y;
    }
    if (tid < 64) sm[KD_OFF + tid * KD_STRIDE + 255] = 0.f; // pad column
    __syncthreads();

    // ---- GEMM1: delta-logits [64 b x 256 n], sigmoid epilogue ----
    {
        const int tb = tid >> 5;          // 0..7  -> b0 = tb*8
        const int tn = tid & 31;          // n = tn + 32*m (strided: bank-free)
        const int b0 = tb * 8;
        float acc[8][8];
        #pragma unroll
        for (int i = 0; i < 8; i++)
            #pragma unroll
            for (int m = 0; m < 8; m++) acc[i][m] = 0.f;

        #pragma unroll 4
        for (int k = 0; k < 64; k++) {
            float a[8], bb[8];
            *(float4*)(a)     = *(const float4*)&sm[QS_OFF + k * QS_STRIDE + b0];
            *(float4*)(a + 4) = *(const float4*)&sm[QS_OFF + k * QS_STRIDE + b0 + 4];
            #pragma unroll
            for (int m = 0; m < 8; m++)
                bb[m] = sm[KD_OFF + k * KD_STRIDE + tn + 32 * m];
            #pragma unroll
            for (int i = 0; i < 8; i++)
                #pragma unroll
                for (int m = 0; m < 8; m++)
                    acc[i][m] = fmaf(a[i], bb[m], acc[i][m]);
        }
        // sigmoid + store sig[b][n] (stride 257 -> conflict-free both ways)
        #pragma unroll
        for (int m = 0; m < 8; m++) {
            int n = tn + 32 * m;
            if (n < SUB_NODES) {
                #pragma unroll
                for (int i = 0; i < 8; i++) {
                    float sg = 1.f / (1.f + __expf(-acc[i][m]));
                    sm[SIG_OFF + (b0 + i) * SG_STRIDE + n] = sg;
                }
            }
        }
    }
    __syncthreads();

    // ---- base prob into cum[0][b]; (phase2) load V into aliased region ----
    if (tid < BT) {
        sm[CUM_OFF + tid] = PHASE2 ? g_probs8[(size_t)s * B_TOTAL + b_base + tid]
                                   : 1.f;
    }
    if (PHASE2) {
        for (int r = w; r < 256; r += 8) {
            int leaf = (s << 8) + (int)(__brev((unsigned)r) >> 24);
            float2 v = *(const float2*)(vtree + (size_t)leaf * DIM + 2 * l);
            *(float2*)&sm[V_OFF + r * 64 + 2 * l] = v;
        }
    }
    __syncthreads();

    // ---- In-place hazard-free expansion over 8 levels ----
    #pragma unroll
    for (int e = 0; e < 8; e++) {
        int half  = 1 << e;
        int items = half * BT;
        for (int it = tid; it < items; it += 256) {
            int b = it & 63, pos = it >> 6;
            float sg = sm[SIG_OFF + b * SG_STRIDE + (half - 1 + pos)];
            float v  = sm[CUM_OFF + pos * 64 + b];
            sm[CUM_OFF + pos * 64 + b]          = v * sg;         // child 0
            sm[CUM_OFF + (pos + half) * 64 + b] = v * (1.f - sg); // child 1
        }
        __syncthreads();
    }

    if (!PHASE2) {
        // write depth-8 probs (convert pos -> standard leaf index)
        for (int it = tid; it < 256 * BT; it += 256) {
            int b = it & 63, pos = it >> 6;
            int leaf8 = (int)(__brev((unsigned)pos) >> 24);
            g_probs8[(size_t)leaf8 * B_TOTAL + b_base + b] =
                sm[CUM_OFF + pos * 64 + b];
        }
    } else {
        // ---- GEMM2: out[64 b x 64 d] += cum[64 x 256] @ V[256 x 64] ----
        const int kg = tid >> 7;          // K split: 2 groups of 128 leaves
        const int t  = tid & 127;
        const int b0 = (t >> 3) * 4;      // 16 b-tiles of 4
        const int d0 = (t & 7) * 8;       // 8  d-tiles of 8
        float acc[4][8];
        #pragma unroll
        for (int i = 0; i < 4; i++)
            #pragma unroll
            for (int j = 0; j < 8; j++) acc[i][j] = 0.f;

        const int l0 = kg * 128;
        #pragma unroll 2
        for (int ll = l0; ll < l0 + 128; ll++) {
            float a[4], vv[8];
            *(float4*)(a)      = *(const float4*)&sm[CUM_OFF + ll * 64 + b0];
            *(float4*)(vv)     = *(const float4*)&sm[V_OFF + ll * 64 + d0];
            *(float4*)(vv + 4) = *(const float4*)&sm[V_OFF + ll * 64 + d0 + 4];
            #pragma unroll
            for (int i = 0; i < 4; i++)
                #pragma unroll
                for (int j = 0; j < 8; j++)
                    acc[i][j] = fmaf(a[i], vv[j], acc[i][j]);
        }
        #pragma unroll
        for (int i = 0; i < 4; i++)
            #pragma unroll
            for (int j = 0; j < 8; j++)
                atomicAdd(&out[(size_t)(b_base + b0 + i) * DIM + d0 + j],
                          acc[i][j]);
    }
}

// ---------------------------------------------------------------------------
extern "C" void kernel_launch(void* const* d_in, const int* in_sizes, int n_in,
                              void* d_out, int out_size) {
    const float* q  = (const float*)d_in[0];   // (2048, 64)
    const float* tk = (const float*)d_in[1];   // (65535, 2, 64)
    const float* tv = (const float*)d_in[2];   // (65536, 64)
    float* out = (float*)d_out;                // (2048, 64)

    cudaFuncSetAttribute(tree_kernel<false>,
                         cudaFuncAttributeMaxDynamicSharedMemorySize, SMEM_BYTES);
    cudaFuncSetAttribute(tree_kernel<true>,
                         cudaFuncAttributeMaxDynamicSharedMemorySize, SMEM_BYTES);

    cudaMemsetAsync(out, 0, (size_t)B_TOTAL * DIM * sizeof(float));
    kdiff_kernel<<<4096, 1024>>>(tk);
    tree_kernel<false><<<B_TOTAL / BT, 256, SMEM_BYTES>>>(q, tv, out);
    tree_kernel<true><<<dim3(NSUB, B_TOTAL / BT), 256, SMEM_BYTES>>>(q, tv, out);
}

// round 3
// speedup vs baseline: 1.0062x; 1.0062x over previous
#include <cuda_runtime.h>
#include <math.h>

// Problem constants
#define B_TOTAL     2048
#define DIM         64
#define NODES_TOTAL 65535
#define SPLIT       8
#define NSUB        256      // 2^SPLIT subtrees
#define SUB_NODES   255      // internal nodes per subtree (8 levels)
#define BT          64       // batch tile per CTA

// Device scratch (static — no allocations allowed)
__device__ float g_kdiff[NODES_TOTAL * DIM];     // k0 - k1 per node
__device__ float g_probs8[NSUB * B_TOTAL];       // [depth8_leaf][batch]

// Shared memory layout (in floats)
#define QS_STRIDE 68
#define KD_STRIDE 260
#define SG_STRIDE 257
#define QS_OFF   0
#define KD_OFF   (QS_OFF + 64 * QS_STRIDE)             // 4352
#define SIG_OFF  (KD_OFF + 64 * KD_STRIDE)             // 20992
#define CUM_OFF  (SIG_OFF + 64 * SG_STRIDE)            // 37440
#define SMEM_FLOATS (CUM_OFF + 256 * 64)               // 53824
#define V_OFF    0   // V aliases Q+K region (dead after GEMM1); 16384 <= 20992
#define SMEM_BYTES (SMEM_FLOATS * 4)                   // 215,296 B

// ---------------------------------------------------------------------------
// K0: kdiff[n][k] = tree_key[n][0][k] - tree_key[n][1][k]
// ---------------------------------------------------------------------------
__global__ void kdiff_kernel(const float* __restrict__ tk) {
    int total = NODES_TOTAL * DIM;
    for (int i = blockIdx.x * blockDim.x + threadIdx.x; i < total;
         i += gridDim.x * blockDim.x) {
        int n = i >> 6, k = i & 63;
        g_kdiff[i] = tk[(n << 7) + k] - tk[(n << 7) + 64 + k];
    }
}

// ---------------------------------------------------------------------------
// Main kernel.  PHASE2=false: top 8 levels -> g_probs8.
//               PHASE2=true : one subtree x 64-batch tile -> atomicAdd(out).
//
// Leaf positions inside a (sub)tree use LSB-first path encoding ("pos"):
// expansion level e writes child0 in place at pos, child1 at pos + 2^e.
// Standard (reference) leaf index = bitrev8(pos); kdiff rows and V rows are
// loaded pre-permuted so all in-kernel indexing is pos-order.
// ---------------------------------------------------------------------------
template <bool PHASE2>
__global__ __launch_bounds__(256, 1)
void tree_kernel(const float* __restrict__ q,
                 const float* __restrict__ vtree,
                 float* __restrict__ out)
{
    extern __shared__ float sm[];
    const int tid    = threadIdx.x;
    const int s      = PHASE2 ? blockIdx.x : 0;                 // subtree id
    const int b_base = (PHASE2 ? blockIdx.y : blockIdx.x) * BT; // batch tile

    const int w = tid >> 5, l = tid & 31;

    // ---- Load Q transposed: Qs[k][b], warp-per-row, lane = 2 floats ----
    for (int b = w; b < BT; b += 8) {
        float2 v = *(const float2*)(q + (size_t)(b_base + b) * DIM + 2 * l);
        sm[QS_OFF + (2 * l)     * QS_STRIDE + b] = v.x;
        sm[QS_OFF + (2 * l + 1) * QS_STRIDE + b] = v.y;
    }

    // ---- Load kdiff transposed, rows in pos-order heap layout ----
    for (int r = w; r < SUB_NODES; r += 8) {
        int rp = r + 1;
        int e  = 31 - __clz(rp);          // level within (sub)tree, 0..7
        int posj = rp - (1 << e);         // LSB-first within-level position
        int j  = e ? (int)(__brev((unsigned)posj) >> (32 - e)) : 0; // std idx
        int lvl = e + (PHASE2 ? SPLIT : 0);
        long node = ((1L << lvl) - 1) + (long)s * (1 << e) + j;
        const float* src = g_kdiff + node * DIM;
        float2 v = *(const float2*)(src + 2 * l);
        sm[KD_OFF + (2 * l)     * KD_STRIDE + r] = v.x;
        sm[KD_OFF + (2 * l + 1) * KD_STRIDE + r] = v.y;
    }
    if (tid < 64) sm[KD_OFF + tid * KD_STRIDE + 255] = 0.f; // pad column
    __syncthreads();

    // ---- GEMM1: delta-logits [64 b x 256 n], sigmoid epilogue ----
    {
        const int tb = tid >> 5;          // 0..7  -> b0 = tb*8
        const int tn = tid & 31;          // n = tn + 32*m (strided: bank-free)
        const int b0 = tb * 8;
        float acc[8][8];
        #pragma unroll
        for (int i = 0; i < 8; i++)
            #pragma unroll
            for (int m = 0; m < 8; m++) acc[i][m] = 0.f;

        #pragma unroll 4
        for (int k = 0; k < 64; k++) {
            float a[8], bb[8];
            *(float4*)(a)     = *(const float4*)&sm[QS_OFF + k * QS_STRIDE + b0];
            *(float4*)(a + 4) = *(const float4*)&sm[QS_OFF + k * QS_STRIDE + b0 + 4];
            #pragma unroll
            for (int m = 0; m < 8; m++)
                bb[m] = sm[KD_OFF + k * KD_STRIDE + tn + 32 * m];
            #pragma unroll
            for (int i = 0; i < 8; i++)
                #pragma unroll
                for (int m = 0; m < 8; m++)
                    acc[i][m] = fmaf(a[i], bb[m], acc[i][m]);
        }
        // sigmoid + store sig[b][n] (stride 257 -> conflict-free both ways)
        #pragma unroll
        for (int m = 0; m < 8; m++) {
            int n = tn + 32 * m;
            if (n < SUB_NODES) {
                #pragma unroll
                for (int i = 0; i < 8; i++) {
                    float sg = 1.f / (1.f + __expf(-acc[i][m]));
                    sm[SIG_OFF + (b0 + i) * SG_STRIDE + n] = sg;
                }
            }
        }
    }
    __syncthreads();

    // ---- base prob into cum[0][b]; (phase2) load V into aliased region ----
    if (tid < BT) {
        sm[CUM_OFF + tid] = PHASE2 ? g_probs8[(size_t)s * B_TOTAL + b_base + tid]
                                   : 1.f;
    }
    if (PHASE2) {
        for (int r = w; r < 256; r += 8) {
            int leaf = (s << 8) + (int)(__brev((unsigned)r) >> 24);
            float2 v = *(const float2*)(vtree + (size_t)leaf * DIM + 2 * l);
            *(float2*)&sm[V_OFF + r * 64 + 2 * l] = v;
        }
    }
    __syncthreads();

    // ---- In-place hazard-free expansion over 8 levels ----
    #pragma unroll
    for (int e = 0; e < 8; e++) {
        int half  = 1 << e;
        int items = half * BT;
        for (int it = tid; it < items; it += 256) {
            int b = it & 63, pos = it >> 6;
            float sg = sm[SIG_OFF + b * SG_STRIDE + (half - 1 + pos)];
            float v  = sm[CUM_OFF + pos * 64 + b];
            sm[CUM_OFF + pos * 64 + b]          = v * sg;         // child 0
            sm[CUM_OFF + (pos + half) * 64 + b] = v * (1.f - sg); // child 1
        }
        __syncthreads();
    }

    if (!PHASE2) {
        // write depth-8 probs (convert pos -> standard leaf index)
        for (int it = tid; it < 256 * BT; it += 256) {
            int b = it & 63, pos = it >> 6;
            int leaf8 = (int)(__brev((unsigned)pos) >> 24);
            g_probs8[(size_t)leaf8 * B_TOTAL + b_base + b] =
                sm[CUM_OFF + pos * 64 + b];
        }
    } else {
        // ---- GEMM2: out[64 b x 64 d] += cum[64 x 256] @ V[256 x 64] ----
        const int kg = tid >> 7;          // K split: 2 groups of 128 leaves
        const int t  = tid & 127;
        const int b0 = (t >> 3) * 4;      // 16 b-tiles of 4
        const int d0 = (t & 7) * 8;       // 8  d-tiles of 8
        float acc[4][8];
        #pragma unroll
        for (int i = 0; i < 4; i++)
            #pragma unroll
            for (int j = 0; j < 8; j++) acc[i][j] = 0.f;

        const int l0 = kg * 128;
        #pragma unroll 2
        for (int ll = l0; ll < l0 + 128; ll++) {
            float a[4], vv[8];
            *(float4*)(a)      = *(const float4*)&sm[CUM_OFF + ll * 64 + b0];
            *(float4*)(vv)     = *(const float4*)&sm[V_OFF + ll * 64 + d0];
            *(float4*)(vv + 4) = *(const float4*)&sm[V_OFF + ll * 64 + d0 + 4];
            #pragma unroll
            for (int i = 0; i < 4; i++)
                #pragma unroll
                for (int j = 0; j < 8; j++)
                    acc[i][j] = fmaf(a[i], vv[j], acc[i][j]);
        }
        #pragma unroll
        for (int i = 0; i < 4; i++)
            #pragma unroll
            for (int j = 0; j < 8; j++)
                atomicAdd(&out[(size_t)(b_base + b0 + i) * DIM + d0 + j],
                          acc[i][j]);
    }
}

// ---------------------------------------------------------------------------
extern "C" void kernel_launch(void* const* d_in, const int* in_sizes, int n_in,
                              void* d_out, int out_size) {
    const float* q  = (const float*)d_in[0];   // (2048, 64)
    const float* tk = (const float*)d_in[1];   // (65535, 2, 64)
    const float* tv = (const float*)d_in[2];   // (65536, 64)
    float* out = (float*)d_out;                // (2048, 64)

    cudaFuncSetAttribute(tree_kernel<false>,
                         cudaFuncAttributeMaxDynamicSharedMemorySize, SMEM_BYTES);
    cudaFuncSetAttribute(tree_kernel<true>,
                         cudaFuncAttributeMaxDynamicSharedMemorySize, SMEM_BYTES);

    cudaMemsetAsync(out, 0, (size_t)B_TOTAL * DIM * sizeof(float));
    kdiff_kernel<<<4096, 1024>>>(tk);
    tree_kernel<false><<<B_TOTAL / BT, 256, SMEM_BYTES>>>(q, tv, out);
    tree_kernel<true><<<dim3(NSUB, B_TOTAL / BT), 256, SMEM_BYTES>>>(q, tv, out);
}

// round 4
// speedup vs baseline: 1.6929x; 1.6825x over previous
#include <cuda_runtime.h>
#include <cuda_bf16.h>
#include <cstdint>

#define NODES_TOTAL 65535
__device__ float g_kdiff[NODES_TOTAL * 64];
__device__ float g_probs8[256 * 2048];

// smem offsets in 16-bit units (halves) / floats
#define HQ   0          // Qh[64][72]
#define HQL  4608       // Ql
#define HKD  9216       // KDh[256][72]
#define HKDL 27648      // KDl            (Q+KD dead after GEMM1)
#define HP   0          // Ph[64][264]  (aliases Q/KD)
#define HPL  16896      // Pl
#define HV   46080      // Vh[256][72]  (aliases sig, spills into dead cum)
#define HVL  64512      // Vl
#define FSIG 23040      // sig f32 [64][257]  @ byte 92160
#define FCUM 39488      // cum f32 [64][257]  @ byte 157952
#define SMEM_BYTES (157952 + 65792)   // 223744

__device__ __forceinline__ uint32_t cvta(const void* p) {
    uint32_t a;
    asm("{.reg .u64 t; cvta.to.shared.u64 t,%1; cvt.u32.u64 %0,t;}" : "=r"(a) : "l"(p));
    return a;
}
__device__ __forceinline__ void ldsm4(uint32_t r[4], uint32_t a) {
    asm volatile("ldmatrix.sync.aligned.m8n8.x4.shared.b16 {%0,%1,%2,%3},[%4];"
        : "=r"(r[0]), "=r"(r[1]), "=r"(r[2]), "=r"(r[3]) : "r"(a));
}
__device__ __forceinline__ void ldsm2(uint32_t r[2], uint32_t a) {
    asm volatile("ldmatrix.sync.aligned.m8n8.x2.shared.b16 {%0,%1},[%2];"
        : "=r"(r[0]), "=r"(r[1]) : "r"(a));
}
__device__ __forceinline__ void ldsm2t(uint32_t r[2], uint32_t a) {
    asm volatile("ldmatrix.sync.aligned.m8n8.x2.trans.shared.b16 {%0,%1},[%2];"
        : "=r"(r[0]), "=r"(r[1]) : "r"(a));
}
__device__ __forceinline__ void mma(float c[4], const uint32_t a[4], const uint32_t b[2]) {
    asm volatile("mma.sync.aligned.m16n8k16.row.col.f32.bf16.bf16.f32 "
        "{%0,%1,%2,%3},{%4,%5,%6,%7},{%8,%9},{%0,%1,%2,%3};"
        : "+f"(c[0]), "+f"(c[1]), "+f"(c[2]), "+f"(c[3])
        : "r"(a[0]), "r"(a[1]), "r"(a[2]), "r"(a[3]), "r"(b[0]), "r"(b[1]));
}
__device__ __forceinline__ void split2(float x, __nv_bfloat16& h, __nv_bfloat16& lo) {
    h = __float2bfloat16(x);
    lo = __float2bfloat16(x - __bfloat162float(h));
}

__global__ void kdiff_kernel(const float* __restrict__ tk) {
    int total = NODES_TOTAL * 64;
    for (int i = blockIdx.x * blockDim.x + threadIdx.x; i < total;
         i += gridDim.x * blockDim.x) {
        int n = i >> 6, k = i & 63;
        g_kdiff[i] = tk[(n << 7) + k] - tk[(n << 7) + 64 + k];
    }
}

template <bool P2>
__global__ __launch_bounds__(256, 1)
void tree_kernel(const float* __restrict__ q, const float* __restrict__ vtree,
                 float* __restrict__ out)
{
    extern __shared__ char sm[];
    __nv_bfloat16* bsm = (__nv_bfloat16*)sm;
    float* fsm = (float*)sm;
    const int tid = threadIdx.x, w = tid >> 5, l = tid & 31;
    const int s = P2 ? blockIdx.y : 0;
    const int b_base = blockIdx.x * 64;
    const uint32_t sb = cvta(sm);

    // ---- Q rows -> split-bf16 [b][k], stride 72 ----
    for (int b = w; b < 64; b += 8) {
        float2 v = *(const float2*)(q + (size_t)(b_base + b) * 64 + 2 * l);
        __nv_bfloat16 h, lo;
        split2(v.x, h, lo); bsm[HQ + b * 72 + 2 * l] = h; bsm[HQL + b * 72 + 2 * l] = lo;
        split2(v.y, h, lo); bsm[HQ + b * 72 + 2 * l + 1] = h; bsm[HQL + b * 72 + 2 * l + 1] = lo;
    }
    // ---- KD rows (heap-pos order) -> split-bf16 [n][k], stride 72 ----
    for (int r = w; r < 255; r += 8) {
        int rp = r + 1, e = 31 - __clz(rp), posj = rp - (1 << e);
        int j = e ? (int)(__brev((unsigned)posj) >> (32 - e)) : 0;
        int lvl = e + (P2 ? 8 : 0);
        const float* src = g_kdiff + (((size_t)1 << lvl) - 1 + (size_t)s * (1 << e) + j) * 64;
        float2 v = *(const float2*)(src + 2 * l);
        __nv_bfloat16 h, lo;
        split2(v.x, h, lo); bsm[HKD + r * 72 + 2 * l] = h; bsm[HKDL + r * 72 + 2 * l] = lo;
        split2(v.y, h, lo); bsm[HKD + r * 72 + 2 * l + 1] = h; bsm[HKDL + r * 72 + 2 * l + 1] = lo;
    }
    if (tid < 64) {  // zero pad row 255
        bsm[HKD + 255 * 72 + tid] = __float2bfloat16(0.f);
        bsm[HKDL + 255 * 72 + tid] = __float2bfloat16(0.f);
    }
    __syncthreads();

    // ---- GEMM1: sig[64b][256n] = sigma(Q . KD^T), split-bf16 HMMA ----
    {
        const int bt = w & 3, nh = w >> 2, g = l >> 2, t = l & 3;
        float acc[16][4];
        #pragma unroll
        for (int i = 0; i < 16; i++)
            #pragma unroll
            for (int j = 0; j < 4; j++) acc[i][j] = 0.f;
        #pragma unroll
        for (int kt = 0; kt < 4; kt++) {
            uint32_t Ah[4], Al[4];
            uint32_t ao = ((16 * bt + (l & 15)) * 72 + kt * 16 + ((l >> 4) << 3)) * 2u;
            ldsm4(Ah, sb + ao);           // HQ = 0
            ldsm4(Al, sb + HQL * 2u + ao);
            #pragma unroll
            for (int nt = 0; nt < 16; nt++) {
                int n0 = 128 * nh + 8 * nt;
                uint32_t bo = ((n0 + (l & 7)) * 72 + kt * 16 + ((l >> 3) & 1) * 8) * 2u;
                uint32_t Bh[2], Bl[2];
                ldsm2(Bh, sb + HKD * 2u + bo);
                ldsm2(Bl, sb + HKDL * 2u + bo);
                mma(acc[nt], Ah, Bh);
                mma(acc[nt], Ah, Bl);
                mma(acc[nt], Al, Bh);
            }
        }
        #pragma unroll
        for (int nt = 0; nt < 16; nt++) {
            int r = 16 * bt + g, c = 128 * nh + 8 * nt + 2 * t;
            fsm[FSIG + r * 257 + c]           = 1.f / (1.f + __expf(-acc[nt][0]));
            fsm[FSIG + r * 257 + c + 1]       = 1.f / (1.f + __expf(-acc[nt][1]));
            fsm[FSIG + (r + 8) * 257 + c]     = 1.f / (1.f + __expf(-acc[nt][2]));
            fsm[FSIG + (r + 8) * 257 + c + 1] = 1.f / (1.f + __expf(-acc[nt][3]));
        }
    }
    __syncthreads();

    // ---- base prob, then in-place expansion: cum[b][pos], stride 257 ----
    if (tid < 64)
        fsm[FCUM + tid * 257] = P2 ? g_probs8[(size_t)s * 2048 + b_base + tid] : 1.f;
    __syncthreads();
    #pragma unroll
    for (int e = 0; e < 8; e++) {
        int half = 1 << e;
        for (int it = tid; it < half * 64; it += 256) {
            int b = it & 63, pos = it >> 6;
            float sg = fsm[FSIG + b * 257 + half - 1 + pos];
            float v = fsm[FCUM + b * 257 + pos];
            fsm[FCUM + b * 257 + pos] = v * sg;
            fsm[FCUM + b * 257 + pos + half] = v * (1.f - sg);
        }
        __syncthreads();
    }

    if (!P2) {
        for (int it = tid; it < 256 * 64; it += 256) {
            int b = it & 63, pos = it >> 6;
            g_probs8[(size_t)(__brev((unsigned)pos) >> 24) * 2048 + b_base + b] =
                fsm[FCUM + b * 257 + pos];
        }
        return;
    }

    // ---- convert cum -> Ph/Pl [b][pos], stride 264 (aliases dead Q/KD) ----
    for (int it = tid; it < 64 * 256; it += 256) {
        int b = it >> 8, pos = it & 255;
        float v = fsm[FCUM + b * 257 + pos];
        __nv_bfloat16 h, lo; split2(v, h, lo);
        bsm[HP + b * 264 + pos] = h;
        bsm[HPL + b * 264 + pos] = lo;
    }
    __syncthreads();   // cum dead; V may overwrite sig + cum head

    // ---- V -> Vh/Vl [pos][d], stride 72 ----
    for (int r = w; r < 256; r += 8) {
        int leaf = (s << 8) + (int)(__brev((unsigned)r) >> 24);
        float2 v = *(const float2*)(vtree + (size_t)leaf * 64 + 2 * l);
        __nv_bfloat16 h, lo;
        split2(v.x, h, lo); bsm[HV + r * 72 + 2 * l] = h; bsm[HVL + r * 72 + 2 * l] = lo;
        split2(v.y, h, lo); bsm[HV + r * 72 + 2 * l + 1] = h; bsm[HVL + r * 72 + 2 * l + 1] = lo;
    }
    __syncthreads();

    // ---- GEMM2: out[64b][64d] += P . V, split-bf16 HMMA ----
    {
        const int bt = w & 3, dh = w >> 2, g = l >> 2, t = l & 3;
        float acc[4][4];
        #pragma unroll
        for (int i = 0; i < 4; i++)
            #pragma unroll
            for (int j = 0; j < 4; j++) acc[i][j] = 0.f;
        #pragma unroll
        for (int kt = 0; kt < 16; kt++) {
            uint32_t Ah[4], Al[4];
            uint32_t ao = ((16 * bt + (l & 15)) * 264 + kt * 16 + ((l >> 4) << 3)) * 2u;
            ldsm4(Ah, sb + ao);           // HP = 0
            ldsm4(Al, sb + HPL * 2u + ao);
            #pragma unroll
            for (int dt = 0; dt < 4; dt++) {
                int d0 = 32 * dh + 8 * dt;
                uint32_t bo = ((kt * 16 + (l & 15)) * 72 + d0) * 2u;
                uint32_t Bh[2], Bl[2];
                ldsm2t(Bh, sb + HV * 2u + bo);
                ldsm2t(Bl, sb + HVL * 2u + bo);
                mma(acc[dt], Ah, Bh);
                mma(acc[dt], Ah, Bl);
                mma(acc[dt], Al, Bh);
            }
        }
        #pragma unroll
        for (int dt = 0; dt < 4; dt++) {
            int r = b_base + 16 * bt + g, c = 32 * dh + 8 * dt + 2 * t;
            atomicAdd(&out[(size_t)r * 64 + c],           acc[dt][0]);
            atomicAdd(&out[(size_t)r * 64 + c + 1],       acc[dt][1]);
            atomicAdd(&out[(size_t)(r + 8) * 64 + c],     acc[dt][2]);
            atomicAdd(&out[(size_t)(r + 8) * 64 + c + 1], acc[dt][3]);
        }
    }
}

extern "C" void kernel_launch(void* const* d_in, const int* in_sizes, int n_in,
                              void* d_out, int out_size) {
    const float* q  = (const float*)d_in[0];
    const float* tk = (const float*)d_in[1];
    const float* tv = (const float*)d_in[2];
    float* out = (float*)d_out;

    cudaFuncSetAttribute(tree_kernel<false>,
                         cudaFuncAttributeMaxDynamicSharedMemorySize, SMEM_BYTES);
    cudaFuncSetAttribute(tree_kernel<true>,
                         cudaFuncAttributeMaxDynamicSharedMemorySize, SMEM_BYTES);

    cudaMemsetAsync(out, 0, (size_t)2048 * 64 * sizeof(float));
    kdiff_kernel<<<4096, 1024>>>(tk);
    tree_kernel<false><<<32, 256, SMEM_BYTES>>>(q, tv, out);
    tree_kernel<true><<<dim3(32, 256), 256, SMEM_BYTES>>>(q, tv, out);
}

// round 5
// speedup vs baseline: 2.5236x; 1.4906x over previous
#include <cuda_runtime.h>
#include <cuda_bf16.h>
#include <cstdint>

// smem layout (bytes)
#define SB_T   0                 // float T[128][257] = 131,584
#define SB_Q   131584            // Qh 18432 | Ql 18432
#define SB_BUF 168448            // 2 bufs x (h 9216 | l 9216)
#define SMEM_BYTES 205312
#define NS 4                     // subtrees per phase-2 CTA

__device__ __align__(256) __nv_bfloat16 g_kdh[256*256*72];
__device__ __align__(256) __nv_bfloat16 g_kdl[256*256*72];
__device__ __align__(256) __nv_bfloat16 g_vh [256*256*72];
__device__ __align__(256) __nv_bfloat16 g_vl [256*256*72];
__device__ __align__(256) __nv_bfloat16 g_qh [2048*72];
__device__ __align__(256) __nv_bfloat16 g_ql [2048*72];
__device__ __align__(256) __nv_bfloat16 g_kth[256*72];
__device__ __align__(256) __nv_bfloat16 g_ktl[256*72];
__device__ float g_probs8[256*2048];

__device__ __forceinline__ uint32_t cvta(const void* p){
    uint32_t a; asm("{.reg .u64 t; cvta.to.shared.u64 t,%1; cvt.u32.u64 %0,t;}":"=r"(a):"l"(p)); return a;
}
__device__ __forceinline__ void ldsm4(uint32_t r[4], uint32_t a){
    asm volatile("ldmatrix.sync.aligned.m8n8.x4.shared.b16 {%0,%1,%2,%3},[%4];"
        :"=r"(r[0]),"=r"(r[1]),"=r"(r[2]),"=r"(r[3]):"r"(a));
}
__device__ __forceinline__ void ldsm2(uint32_t r[2], uint32_t a){
    asm volatile("ldmatrix.sync.aligned.m8n8.x2.shared.b16 {%0,%1},[%2];"
        :"=r"(r[0]),"=r"(r[1]):"r"(a));
}
__device__ __forceinline__ void ldsm2t(uint32_t r[2], uint32_t a){
    asm volatile("ldmatrix.sync.aligned.m8n8.x2.trans.shared.b16 {%0,%1},[%2];"
        :"=r"(r[0]),"=r"(r[1]):"r"(a));
}
__device__ __forceinline__ void mma(float c[4], const uint32_t a[4], const uint32_t b[2]){
    asm volatile("mma.sync.aligned.m16n8k16.row.col.f32.bf16.bf16.f32 "
        "{%0,%1,%2,%3},{%4,%5,%6,%7},{%8,%9},{%0,%1,%2,%3};"
        :"+f"(c[0]),"+f"(c[1]),"+f"(c[2]),"+f"(c[3])
        :"r"(a[0]),"r"(a[1]),"r"(a[2]),"r"(a[3]),"r"(b[0]),"r"(b[1]));
}
__device__ __forceinline__ uint32_t prmt(uint32_t a, uint32_t b, uint32_t s){
    uint32_t r; asm("prmt.b32 %0,%1,%2,%3;":"=r"(r):"r"(a),"r"(b),"r"(s)); return r;
}
__device__ __forceinline__ void cp16(uint32_t d, const void* s){
    asm volatile("cp.async.cg.shared.global [%0],[%1],16;"::"r"(d),"l"(s));
}
#define CP_COMMIT() asm volatile("cp.async.commit_group;" ::: "memory")
#define CP_WAIT(N)  asm volatile("cp.async.wait_group %0;" :: "n"(N) : "memory")
__device__ __forceinline__ void split2(float x, __nv_bfloat16& h, __nv_bfloat16& lo){
    h = __float2bfloat16(x); lo = __float2bfloat16(x - __bfloat162float(h));
}
__device__ __forceinline__ uint32_t packsplit(float x){
    __nv_bfloat16 h, lo; split2(x, h, lo);
    return (uint32_t)__bfloat16_as_ushort(h) | ((uint32_t)__bfloat16_as_ushort(lo) << 16);
}

// ----------------------------- prep kernels -----------------------------
__global__ void prep_kd(const float* __restrict__ tk){
    int bx = blockIdx.x, s = bx >> 8, r = bx & 255, k = threadIdx.x;
    float d = 0.f;
    if (r < 255 && k < 64){
        int rp = r+1, e = 31-__clz(rp), pj = rp-(1<<e);
        int j = e ? (int)(__brev((unsigned)pj) >> (32-e)) : 0;
        size_t node = (((size_t)1<<(e+8))-1) + (size_t)s*(1<<e) + j;
        d = tk[node*128 + k] - tk[node*128 + 64 + k];
    }
    __nv_bfloat16 h, lo; split2(d, h, lo);
    g_kdh[(size_t)bx*72 + k] = h; g_kdl[(size_t)bx*72 + k] = lo;
}
__global__ void prep_top(const float* __restrict__ tk){
    int r = blockIdx.x, k = threadIdx.x;
    float d = 0.f;
    if (r < 255 && k < 64){
        int rp = r+1, e = 31-__clz(rp), pj = rp-(1<<e);
        int j = e ? (int)(__brev((unsigned)pj) >> (32-e)) : 0;
        size_t node = ((size_t)1<<e)-1 + j;
        d = tk[node*128 + k] - tk[node*128 + 64 + k];
    }
    __nv_bfloat16 h, lo; split2(d, h, lo);
    g_kth[r*72 + k] = h; g_ktl[r*72 + k] = lo;
}
__global__ void prep_v(const float* __restrict__ tv){
    int bx = blockIdx.x, s = bx >> 8, r = bx & 255, k = threadIdx.x;
    size_t leaf = (size_t)s*256 + (__brev((unsigned)r) >> 24);
    float v = (k < 64) ? tv[leaf*64 + k] : 0.f;
    __nv_bfloat16 h, lo; split2(v, h, lo);
    g_vh[(size_t)bx*72 + k] = h; g_vl[(size_t)bx*72 + k] = lo;
}
__global__ void prep_q(const float* __restrict__ q){
    int b = blockIdx.x, k = threadIdx.x;
    float v = (k < 64) ? q[b*64 + k] : 0.f;
    __nv_bfloat16 h, lo; split2(v, h, lo);
    g_qh[b*72 + k] = h; g_ql[b*72 + k] = lo;
}

// ----------------------------- main kernel -----------------------------
template <bool P2>
__global__ __launch_bounds__(512, 1)
void tree_kernel(float* __restrict__ out)
{
    extern __shared__ char smc[];
    float* fT = (float*)smc;
    uint32_t* uT = (uint32_t*)smc;
    const uint32_t SB = cvta(smc);
    const int tid = threadIdx.x, w = tid >> 5, l = tid & 31;
    const int btile = blockIdx.x, sg = blockIdx.y;
    const int b_base = btile * 128;
    const int bt = w & 7, grp = w >> 3;          // warp tile coords
    const int nsub = P2 ? NS : 1;
    const int cps  = P2 ? 8 : 4;                 // chunks per subtree
    const int total = nsub * cps;

    auto issue = [&](int t){
        int c = t & 7, si = t >> 3;
        const __nv_bfloat16 *ph, *pl;
        if (P2){
            size_t off = ((size_t)(sg*NS + si)*256 + (size_t)(c & 3)*64)*72;
            if (c < 4){ ph = g_kdh + off; pl = g_kdl + off; }
            else      { ph = g_vh  + off; pl = g_vl  + off; }
        } else {
            size_t off = (size_t)(c*64)*72; ph = g_kth + off; pl = g_ktl + off;
        }
        uint32_t dst = SB + SB_BUF + (uint32_t)(t & 1)*18432;
        for (int i = tid; i < 576; i += 512){
            cp16(dst + i*16,        (const char*)ph + i*16);
            cp16(dst + 9216 + i*16, (const char*)pl + i*16);
        }
        CP_COMMIT();
    };

    // Q copy (bundled into group 0 with chunk 0)
    {
        const char* qh = (const char*)g_qh + (size_t)btile*18432;
        const char* ql = (const char*)g_ql + (size_t)btile*18432;
        for (int i = tid; i < 1152; i += 512){
            cp16(SB + SB_Q + i*16,         qh + i*16);
            cp16(SB + SB_Q + 18432 + i*16, ql + i*16);
        }
    }
    issue(0);
    if (total > 1) issue(1);

    float acc2[4][4];
    #pragma unroll
    for (int i = 0; i < 4; i++)
        #pragma unroll
        for (int j = 0; j < 4; j++) acc2[i][j] = 0.f;

    for (int si = 0; si < nsub; si++){
        const int s = P2 ? sg*NS + si : 0;
        // ---------------- GEMM1: 4 n-chunk passes ----------------
        for (int p = 0; p < 4; p++){
            int t = si*cps + p;
            if (t + 1 < total) CP_WAIT(1); else CP_WAIT(0);
            __syncthreads();
            uint32_t kb = SB + SB_BUF + (uint32_t)(t & 1)*18432;
            float a1[4][4];
            #pragma unroll
            for (int i = 0; i < 4; i++)
                #pragma unroll
                for (int j = 0; j < 4; j++) a1[i][j] = 0.f;
            #pragma unroll
            for (int kt = 0; kt < 4; kt++){
                uint32_t Ah[4], Al[4];
                uint32_t ao = SB + SB_Q +
                    (uint32_t)(((bt*16 + (l & 15))*72 + kt*16 + ((l >> 4) << 3)) << 1);
                ldsm4(Ah, ao); ldsm4(Al, ao + 18432);
                #pragma unroll
                for (int nt = 0; nt < 4; nt++){
                    uint32_t bo = kb +
                        (uint32_t)(((grp*32 + nt*8 + (l & 7))*72 + kt*16 + (((l >> 3) & 1) << 3)) << 1);
                    uint32_t Bh[2], Bl[2]; ldsm2(Bh, bo); ldsm2(Bl, bo + 9216);
                    mma(a1[nt], Ah, Bh); mma(a1[nt], Ah, Bl); mma(a1[nt], Al, Bh);
                }
            }
            // logits -> T slots [1 + node]
            #pragma unroll
            for (int nt = 0; nt < 4; nt++){
                int r = bt*16 + (l >> 2);
                int cc = p*64 + grp*32 + nt*8 + 2*(l & 3);
                fT[r*257 + 1 + cc]       = a1[nt][0];
                fT[r*257 + 2 + cc]       = a1[nt][1];
                fT[(r+8)*257 + 1 + cc]   = a1[nt][2];
                fT[(r+8)*257 + 2 + cc]   = a1[nt][3];
            }
            __syncthreads();
            if (t + 2 < total) issue(t + 2);
        }
        // base probability into slot 0
        if (tid < 128)
            fT[tid*257] = P2 ? g_probs8[(size_t)s*2048 + b_base + tid] : 1.f;
        __syncthreads();

        // ---------------- expansion (warp-private batches) ----------------
        {
            const int wb = w * 8;
            #pragma unroll
            for (int e = 0; e < 7; e++){
                int half = 1 << e;
                for (int it = l; it < 8*half; it += 32){
                    int b = wb + (it & 7), pos = it >> 3;
                    float x  = fT[b*257 + half + pos];
                    float sg0 = 1.f / (1.f + __expf(-x));
                    float v  = fT[b*257 + pos];
                    float c0 = v * sg0;
                    fT[b*257 + pos]        = c0;
                    fT[b*257 + pos + half] = v - c0;
                }
                __syncwarp();
            }
            for (int it = l; it < 1024; it += 32){   // level 7
                int b = wb + (it & 7), pos = it >> 3;
                float x  = fT[b*257 + 128 + pos];
                float sg0 = 1.f / (1.f + __expf(-x));
                float v  = fT[b*257 + pos];
                float c0 = v * sg0, c1 = v - c0;
                if (P2){
                    uT[b*257 + pos]       = packsplit(c0);
                    uT[b*257 + pos + 128] = packsplit(c1);
                } else {
                    fT[b*257 + pos]       = c0;
                    fT[b*257 + pos + 128] = c1;
                }
            }
        }
        __syncthreads();

        if (!P2){
            for (int it = tid; it < 128*256; it += 512){
                int b = it & 127, pos = it >> 7;
                g_probs8[(size_t)(__brev((unsigned)pos) >> 24)*2048 + b_base + b] =
                    fT[b*257 + pos];
            }
            return;
        }

        // ---------------- GEMM2: 4 k-chunks, acc in registers ----------------
        for (int c = 0; c < 4; c++){
            int t = si*8 + 4 + c;
            if (t + 1 < total) CP_WAIT(1); else CP_WAIT(0);
            __syncthreads();
            uint32_t vb = SB + SB_BUF + (uint32_t)(t & 1)*18432;
            #pragma unroll
            for (int kt = 0; kt < 4; kt++){
                int r0 = bt*16 + (l >> 2);
                int k0 = kt*16 + 2*(l & 3);          // local to chunk; leaves in T at c*64+...
                int kk = c*64 + k0;
                uint32_t Ah[4], Al[4];
                {
                    uint32_t p0 = uT[r0*257 + kk],       p1 = uT[r0*257 + kk + 1];
                    Ah[0] = prmt(p0, p1, 0x5410); Al[0] = prmt(p0, p1, 0x7632);
                    p0 = uT[(r0+8)*257 + kk];     p1 = uT[(r0+8)*257 + kk + 1];
                    Ah[1] = prmt(p0, p1, 0x5410); Al[1] = prmt(p0, p1, 0x7632);
                    p0 = uT[r0*257 + kk + 8];     p1 = uT[r0*257 + kk + 9];
                    Ah[2] = prmt(p0, p1, 0x5410); Al[2] = prmt(p0, p1, 0x7632);
                    p0 = uT[(r0+8)*257 + kk + 8]; p1 = uT[(r0+8)*257 + kk + 9];
                    Ah[3] = prmt(p0, p1, 0x5410); Al[3] = prmt(p0, p1, 0x7632);
                }
                #pragma unroll
                for (int dt = 0; dt < 4; dt++){
                    uint32_t bo = vb +
                        (uint32_t)(((kt*16 + (l & 15))*72 + grp*32 + dt*8) << 1);
                    uint32_t Bh[2], Bl[2]; ldsm2t(Bh, bo); ldsm2t(Bl, bo + 9216);
                    mma(acc2[dt], Ah, Bh); mma(acc2[dt], Ah, Bl); mma(acc2[dt], Al, Bh);
                }
            }
            __syncthreads();
            if (t + 2 < total) issue(t + 2);
        }
    }

    // ---------------- epilogue: one atomic pass ----------------
    #pragma unroll
    for (int dt = 0; dt < 4; dt++){
        int r = b_base + bt*16 + (l >> 2);
        int cc = grp*32 + dt*8 + 2*(l & 3);
        atomicAdd(&out[(size_t)r*64 + cc],         acc2[dt][0]);
        atomicAdd(&out[(size_t)r*64 + cc + 1],     acc2[dt][1]);
        atomicAdd(&out[(size_t)(r+8)*64 + cc],     acc2[dt][2]);
        atomicAdd(&out[(size_t)(r+8)*64 + cc + 1], acc2[dt][3]);
    }
}

extern "C" void kernel_launch(void* const* d_in, const int* in_sizes, int n_in,
                              void* d_out, int out_size) {
    const float* q  = (const float*)d_in[0];
    const float* tk = (const float*)d_in[1];
    const float* tv = (const float*)d_in[2];
    float* out = (float*)d_out;

    cudaFuncSetAttribute(tree_kernel<false>,
                         cudaFuncAttributeMaxDynamicSharedMemorySize, SMEM_BYTES);
    cudaFuncSetAttribute(tree_kernel<true>,
                         cudaFuncAttributeMaxDynamicSharedMemorySize, SMEM_BYTES);

    prep_kd<<<65536, 72>>>(tk);
    prep_top<<<256, 72>>>(tk);
    prep_v<<<65536, 72>>>(tv);
    prep_q<<<2048, 72>>>(q);
    cudaMemsetAsync(out, 0, (size_t)2048 * 64 * sizeof(float));
    tree_kernel<false><<<dim3(16, 1),  512, SMEM_BYTES>>>(out);
    tree_kernel<true ><<<dim3(16, 64), 512, SMEM_BYTES>>>(out);
}

// round 6
// speedup vs baseline: 2.7818x; 1.1023x over previous
#include <cuda_runtime.h>
#include <cuda_bf16.h>
#include <cstdint>

// smem (bytes): T = float[64][257] = 65792, then 2 x 18432 chunk buffers
#define SB_BUF 65792
#define SMEM_BYTES (65792 + 2*18432)   // 102656 -> 2 CTAs/SM
#define NS 4                           // subtrees per phase-2 CTA

__device__ __align__(256) __nv_bfloat16 g_kdh[256*256*72];
__device__ __align__(256) __nv_bfloat16 g_kdl[256*256*72];
__device__ __align__(256) __nv_bfloat16 g_vh [256*256*72];
__device__ __align__(256) __nv_bfloat16 g_vl [256*256*72];
__device__ __align__(256) __nv_bfloat16 g_qh [2048*72];
__device__ __align__(256) __nv_bfloat16 g_ql [2048*72];
__device__ __align__(256) __nv_bfloat16 g_kth[256*72];
__device__ __align__(256) __nv_bfloat16 g_ktl[256*72];
__device__ float g_probs8[256*2048];

__device__ __forceinline__ uint32_t cvta(const void* p){
    uint32_t a; asm("{.reg .u64 t; cvta.to.shared.u64 t,%1; cvt.u32.u64 %0,t;}":"=r"(a):"l"(p)); return a;
}
__device__ __forceinline__ void ldsm2(uint32_t r[2], uint32_t a){
    asm volatile("ldmatrix.sync.aligned.m8n8.x2.shared.b16 {%0,%1},[%2];"
        :"=r"(r[0]),"=r"(r[1]):"r"(a));
}
__device__ __forceinline__ void ldsm2t(uint32_t r[2], uint32_t a){
    asm volatile("ldmatrix.sync.aligned.m8n8.x2.trans.shared.b16 {%0,%1},[%2];"
        :"=r"(r[0]),"=r"(r[1]):"r"(a));
}
__device__ __forceinline__ void mma(float c[4], const uint32_t a[4], const uint32_t b[2]){
    asm volatile("mma.sync.aligned.m16n8k16.row.col.f32.bf16.bf16.f32 "
        "{%0,%1,%2,%3},{%4,%5,%6,%7},{%8,%9},{%0,%1,%2,%3};"
        :"+f"(c[0]),"+f"(c[1]),"+f"(c[2]),"+f"(c[3])
        :"r"(a[0]),"r"(a[1]),"r"(a[2]),"r"(a[3]),"r"(b[0]),"r"(b[1]));
}
__device__ __forceinline__ uint32_t prmt(uint32_t a, uint32_t b, uint32_t s){
    uint32_t r; asm("prmt.b32 %0,%1,%2,%3;":"=r"(r):"r"(a),"r"(b),"r"(s)); return r;
}
__device__ __forceinline__ void cp16(uint32_t d, const void* s){
    asm volatile("cp.async.cg.shared.global [%0],[%1],16;"::"r"(d),"l"(s));
}
#define CP_COMMIT() asm volatile("cp.async.commit_group;" ::: "memory")
#define CP_WAIT(N)  asm volatile("cp.async.wait_group %0;" :: "n"(N) : "memory")
__device__ __forceinline__ void split2(float x, __nv_bfloat16& h, __nv_bfloat16& lo){
    h = __float2bfloat16(x); lo = __float2bfloat16(x - __bfloat162float(h));
}
__device__ __forceinline__ uint32_t packsplit(float x){
    __nv_bfloat16 h, lo; split2(x, h, lo);
    return (uint32_t)__bfloat16_as_ushort(h) | ((uint32_t)__bfloat16_as_ushort(lo) << 16);
}
__device__ __forceinline__ float fast_sigmoid(float x){
    float e; asm("ex2.approx.f32 %0, %1;" : "=f"(e) : "f"(-x * 1.4426950408889634f));
    float r; asm("rcp.approx.f32 %0, %1;" : "=f"(r) : "f"(1.f + e));
    return r;
}

// ----------------------------- prep kernels -----------------------------
__global__ void prep_kd(const float* __restrict__ tk){
    int bx = blockIdx.x, s = bx >> 8, r = bx & 255, k = threadIdx.x;
    float d = 0.f;
    if (r < 255 && k < 64){
        int rp = r+1, e = 31-__clz(rp), pj = rp-(1<<e);
        int j = e ? (int)(__brev((unsigned)pj) >> (32-e)) : 0;
        size_t node = (((size_t)1<<(e+8))-1) + (size_t)s*(1<<e) + j;
        d = tk[node*128 + k] - tk[node*128 + 64 + k];
    }
    __nv_bfloat16 h, lo; split2(d, h, lo);
    g_kdh[(size_t)bx*72 + k] = h; g_kdl[(size_t)bx*72 + k] = lo;
}
__global__ void prep_top(const float* __restrict__ tk){
    int r = blockIdx.x, k = threadIdx.x;
    float d = 0.f;
    if (r < 255 && k < 64){
        int rp = r+1, e = 31-__clz(rp), pj = rp-(1<<e);
        int j = e ? (int)(__brev((unsigned)pj) >> (32-e)) : 0;
        size_t node = ((size_t)1<<e)-1 + j;
        d = tk[node*128 + k] - tk[node*128 + 64 + k];
    }
    __nv_bfloat16 h, lo; split2(d, h, lo);
    g_kth[r*72 + k] = h; g_ktl[r*72 + k] = lo;
}
__global__ void prep_v(const float* __restrict__ tv){
    int bx = blockIdx.x, s = bx >> 8, r = bx & 255, k = threadIdx.x;
    size_t leaf = (size_t)s*256 + (__brev((unsigned)r) >> 24);
    float v = (k < 64) ? tv[leaf*64 + k] : 0.f;
    __nv_bfloat16 h, lo; split2(v, h, lo);
    g_vh[(size_t)bx*72 + k] = h; g_vl[(size_t)bx*72 + k] = lo;
}
__global__ void prep_q(const float* __restrict__ q){
    int b = blockIdx.x, k = threadIdx.x;
    float v = (k < 64) ? q[b*64 + k] : 0.f;
    __nv_bfloat16 h, lo; split2(v, h, lo);
    g_qh[b*72 + k] = h; g_ql[b*72 + k] = lo;
}

// ----------------------------- main kernel -----------------------------
template <bool P2>
__global__ __launch_bounds__(256, 2)
void tree_kernel(float* __restrict__ out)
{
    extern __shared__ char smc[];
    float* fT = (float*)smc;
    uint32_t* uT = (uint32_t*)smc;
    const uint32_t SB = cvta(smc);
    const int tid = threadIdx.x, w = tid >> 5, l = tid & 31;
    const int btile = blockIdx.x, sg = blockIdx.y;
    const int b_base = btile * 64;
    const int bt = w & 3, grp = w >> 2;          // 4 row-tiles x 2 col-halves
    const int nsub = P2 ? NS : 1;
    const int cps  = P2 ? 8 : 4;
    const int total = nsub * cps;

    auto issue = [&](int t){
        int c = t & 7, si = t >> 3;
        const __nv_bfloat16 *ph, *pl;
        if (P2){
            size_t off = ((size_t)(sg*NS + si)*256 + (size_t)(c & 3)*64)*72;
            if (c < 4){ ph = g_kdh + off; pl = g_kdl + off; }
            else      { ph = g_vh  + off; pl = g_vl  + off; }
        } else {
            size_t off = (size_t)(c*64)*72; ph = g_kth + off; pl = g_ktl + off;
        }
        uint32_t dst = SB + SB_BUF + (uint32_t)(t & 1)*18432;
        for (int i = tid; i < 576; i += 256){
            cp16(dst + i*16,        (const char*)ph + i*16);
            cp16(dst + 9216 + i*16, (const char*)pl + i*16);
        }
        CP_COMMIT();
    };

    // ---- Q fragments -> registers (direct fragment-indexed global loads) ----
    uint32_t QAh[4][4], QAl[4][4];
    {
        int r0 = b_base + bt*16 + (l >> 2);
        int c0 = 2 * (l & 3);
        #pragma unroll
        for (int kt = 0; kt < 4; kt++){
            int k0 = kt*16 + c0;
            QAh[kt][0] = *(const uint32_t*)&g_qh[(size_t)r0*72 + k0];
            QAh[kt][1] = *(const uint32_t*)&g_qh[(size_t)(r0+8)*72 + k0];
            QAh[kt][2] = *(const uint32_t*)&g_qh[(size_t)r0*72 + k0 + 8];
            QAh[kt][3] = *(const uint32_t*)&g_qh[(size_t)(r0+8)*72 + k0 + 8];
            QAl[kt][0] = *(const uint32_t*)&g_ql[(size_t)r0*72 + k0];
            QAl[kt][1] = *(const uint32_t*)&g_ql[(size_t)(r0+8)*72 + k0];
            QAl[kt][2] = *(const uint32_t*)&g_ql[(size_t)r0*72 + k0 + 8];
            QAl[kt][3] = *(const uint32_t*)&g_ql[(size_t)(r0+8)*72 + k0 + 8];
        }
    }

    issue(0);
    if (total > 1) issue(1);

    float acc2[4][4];
    #pragma unroll
    for (int i = 0; i < 4; i++)
        #pragma unroll
        for (int j = 0; j < 4; j++) acc2[i][j] = 0.f;

    for (int si = 0; si < nsub; si++){
        const int s = P2 ? sg*NS + si : 0;
        // ---------------- GEMM1: 4 passes of 64 n-columns ----------------
        for (int p = 0; p < 4; p++){
            int t = si*cps + p;
            if (t + 1 < total) CP_WAIT(1); else CP_WAIT(0);
            __syncthreads();
            uint32_t kb = SB + SB_BUF + (uint32_t)(t & 1)*18432;
            float a1[4][4];
            #pragma unroll
            for (int i = 0; i < 4; i++)
                #pragma unroll
                for (int j = 0; j < 4; j++) a1[i][j] = 0.f;
            #pragma unroll
            for (int kt = 0; kt < 4; kt++){
                #pragma unroll
                for (int nt = 0; nt < 4; nt++){
                    uint32_t bo = kb +
                        (uint32_t)(((grp*32 + nt*8 + (l & 7))*72 + kt*16 + (((l >> 3) & 1) << 3)) << 1);
                    uint32_t Bh[2], Bl[2]; ldsm2(Bh, bo); ldsm2(Bl, bo + 9216);
                    mma(a1[nt], QAh[kt], Bh); mma(a1[nt], QAh[kt], Bl); mma(a1[nt], QAl[kt], Bh);
                }
            }
            #pragma unroll
            for (int nt = 0; nt < 4; nt++){
                int r = bt*16 + (l >> 2);
                int cc = p*64 + grp*32 + nt*8 + 2*(l & 3);
                fT[r*257 + 1 + cc]     = a1[nt][0];
                fT[r*257 + 2 + cc]     = a1[nt][1];
                fT[(r+8)*257 + 1 + cc] = a1[nt][2];
                fT[(r+8)*257 + 2 + cc] = a1[nt][3];
            }
            __syncthreads();
            if (t + 2 < total) issue(t + 2);
        }
        if (tid < 64)
            fT[tid*257] = P2 ? g_probs8[(size_t)s*2048 + b_base + tid] : 1.f;
        __syncthreads();

        // ---------------- expansion (warp-private 8 batches) ----------------
        {
            const int wb = w * 8;
            #pragma unroll
            for (int e = 0; e < 7; e++){
                int half = 1 << e;
                for (int it = l; it < 8*half; it += 32){
                    int b = wb + (it & 7), pos = it >> 3;
                    float sg0 = fast_sigmoid(fT[b*257 + half + pos]);
                    float v = fT[b*257 + pos];
                    float c0 = v * sg0;
                    fT[b*257 + pos]        = c0;
                    fT[b*257 + pos + half] = v - c0;
                }
                __syncwarp();
            }
            for (int it = l; it < 1024; it += 32){   // level 7
                int b = wb + (it & 7), pos = it >> 3;
                float sg0 = fast_sigmoid(fT[b*257 + 128 + pos]);
                float v = fT[b*257 + pos];
                float c0 = v * sg0, c1 = v - c0;
                if (P2){
                    uT[b*257 + pos]       = packsplit(c0);
                    uT[b*257 + pos + 128] = packsplit(c1);
                } else {
                    fT[b*257 + pos]       = c0;
                    fT[b*257 + pos + 128] = c1;
                }
            }
        }
        __syncthreads();

        if (!P2){
            for (int it = tid; it < 64*256; it += 256){
                int b = it & 63, pos = it >> 6;
                g_probs8[(size_t)(__brev((unsigned)pos) >> 24)*2048 + b_base + b] =
                    fT[b*257 + pos];
            }
            return;
        }

        // ---------------- GEMM2: 4 k-chunks, register accumulator ----------------
        for (int c = 0; c < 4; c++){
            int t = si*8 + 4 + c;
            if (t + 1 < total) CP_WAIT(1); else CP_WAIT(0);
            __syncthreads();
            uint32_t vb = SB + SB_BUF + (uint32_t)(t & 1)*18432;
            #pragma unroll
            for (int kt = 0; kt < 4; kt++){
                int r0 = bt*16 + (l >> 2);
                int kk = c*64 + kt*16 + 2*(l & 3);
                uint32_t Ah[4], Al[4];
                {
                    uint32_t p0 = uT[r0*257 + kk],       p1 = uT[r0*257 + kk + 1];
                    Ah[0] = prmt(p0, p1, 0x5410); Al[0] = prmt(p0, p1, 0x7632);
                    p0 = uT[(r0+8)*257 + kk];     p1 = uT[(r0+8)*257 + kk + 1];
                    Ah[1] = prmt(p0, p1, 0x5410); Al[1] = prmt(p0, p1, 0x7632);
                    p0 = uT[r0*257 + kk + 8];     p1 = uT[r0*257 + kk + 9];
                    Ah[2] = prmt(p0, p1, 0x5410); Al[2] = prmt(p0, p1, 0x7632);
                    p0 = uT[(r0+8)*257 + kk + 8]; p1 = uT[(r0+8)*257 + kk + 9];
                    Ah[3] = prmt(p0, p1, 0x5410); Al[3] = prmt(p0, p1, 0x7632);
                }
                #pragma unroll
                for (int dt = 0; dt < 4; dt++){
                    uint32_t bo = vb +
                        (uint32_t)(((kt*16 + (l & 15))*72 + grp*32 + dt*8) << 1);
                    uint32_t Bh[2], Bl[2]; ldsm2t(Bh, bo); ldsm2t(Bl, bo + 9216);
                    mma(acc2[dt], Ah, Bh); mma(acc2[dt], Ah, Bl); mma(acc2[dt], Al, Bh);
                }
            }
            __syncthreads();
            if (t + 2 < total) issue(t + 2);
        }
    }

    // ---------------- epilogue: one atomic pass per CTA ----------------
    #pragma unroll
    for (int dt = 0; dt < 4; dt++){
        int r = b_base + bt*16 + (l >> 2);
        int cc = grp*32 + dt*8 + 2*(l & 3);
        atomicAdd(&out[(size_t)r*64 + cc],         acc2[dt][0]);
        atomicAdd(&out[(size_t)r*64 + cc + 1],     acc2[dt][1]);
        atomicAdd(&out[(size_t)(r+8)*64 + cc],     acc2[dt][2]);
        atomicAdd(&out[(size_t)(r+8)*64 + cc + 1], acc2[dt][3]);
    }
}

extern "C" void kernel_launch(void* const* d_in, const int* in_sizes, int n_in,
                              void* d_out, int out_size) {
    const float* q  = (const float*)d_in[0];
    const float* tk = (const float*)d_in[1];
    const float* tv = (const float*)d_in[2];
    float* out = (float*)d_out;

    cudaFuncSetAttribute(tree_kernel<false>,
                         cudaFuncAttributeMaxDynamicSharedMemorySize, SMEM_BYTES);
    cudaFuncSetAttribute(tree_kernel<true>,
                         cudaFuncAttributeMaxDynamicSharedMemorySize, SMEM_BYTES);

    prep_kd<<<65536, 72>>>(tk);
    prep_top<<<256, 72>>>(tk);
    prep_v<<<65536, 72>>>(tv);
    prep_q<<<2048, 72>>>(q);
    cudaMemsetAsync(out, 0, (size_t)2048 * 64 * sizeof(float));
    tree_kernel<false><<<dim3(32, 1),  256, SMEM_BYTES>>>(out);
    tree_kernel<true ><<<dim3(32, 64), 256, SMEM_BYTES>>>(out);
}